// round 8
// baseline (speedup 1.0000x reference)
#include <cuda_runtime.h>
#include <cstdint>
#include <cstddef>

#define NC 10
#define DD 512
#define D4 128          // DD/4
#define SEG_BLOCKS 296
#define SEG_GROUPS (SEG_BLOCKS * 4)
#define SEG_SMEM (4 * NC * D4 * 16)   // 81920 bytes

// k_logits pipeline geometry
#define TILE_ROWS 64
#define SLICE_F4  8                   // 8 float4 = 32 dims per slice
#define NSLICES   (D4 / SLICE_F4)     // 16
#define NSTAGES   4
#define SLICE_BYTES (TILE_ROWS * SLICE_F4 * 16)   // 8192
#define PIPE_SMEM (NSTAGES * SLICE_BYTES)         // 32768

typedef unsigned long long ull;

// Scratch (no cudaMalloc allowed)
__device__ float4 g_part4[SEG_BLOCKS * NC * D4];   // 6.06 MB partial sums
__device__ int    g_cnt_part[SEG_BLOCKS * NC];
__device__ float4 g_sums4[NC * D4];
__device__ float4 g_proto4[NC * D4];
__device__ float  g_sqp[NC];
__device__ float  g_loss;

// Packed f32x2 FMA (Blackwell): elementwise d = a*b + c on two packed floats.
static __device__ __forceinline__ ull fma2(ull a, ull b, ull c) {
    ull d;
    asm("fma.rn.f32x2 %0, %1, %2, %3;" : "=l"(d) : "l"(a), "l"(b), "l"(c));
    return d;
}
static __device__ __forceinline__ float u64_sum2(ull v) {
    float lo, hi;
    asm("mov.b64 {%0,%1}, %2;" : "=f"(lo), "=f"(hi) : "l"(v));
    return lo + hi;
}
static __device__ __forceinline__ uint32_t smem_u32(const void* p) {
    uint32_t a;
    asm("{ .reg .u64 t; cvta.to.shared.u64 t, %1; cvt.u32.u64 %0, t; }"
        : "=r"(a) : "l"(p));
    return a;
}
static __device__ __forceinline__ void cp_async16(uint32_t dst, const void* src) {
    asm volatile("cp.async.cg.shared.global [%0], [%1], 16;"
                 :: "r"(dst), "l"(src));
}

// ---------------------------------------------------------------------------
// K1: segment sums. 512 threads = 4 independent row-groups of 128, each with
// its own 20KB smem replica -> RMW chain depth 1 per row. Partials to global.
// ---------------------------------------------------------------------------
__global__ __launch_bounds__(512) void k_segsum(const float4* __restrict__ E4,
                                                const int* __restrict__ labels,
                                                int nrows) {
    extern __shared__ float4 sm4[];            // [4][NC][D4]
    __shared__ int scnt[NC];
    const int g = threadIdx.x >> 7;            // group 0..3
    const int t = threadIdx.x & 127;           // float4 column
    float4* rep = sm4 + g * (NC * D4);

    if (threadIdx.x < NC) scnt[threadIdx.x] = 0;
#pragma unroll
    for (int c = 0; c < NC; c++) rep[c * D4 + t] = make_float4(0.f, 0.f, 0.f, 0.f);
    __syncthreads();

    const int  gid    = blockIdx.x * 4 + g;
    const long stride = (long)SEG_GROUPS * 4;
    for (long r0 = (long)gid * 4; r0 < nrows; r0 += stride) {
        if (r0 + 4 <= nrows) {
            const int4 lab4 = *(const int4*)(labels + r0);
            float4 v0 = E4[(size_t)(r0 + 0) * D4 + t];
            float4 v1 = E4[(size_t)(r0 + 1) * D4 + t];
            float4 v2 = E4[(size_t)(r0 + 2) * D4 + t];
            float4 v3 = E4[(size_t)(r0 + 3) * D4 + t];
            if (t == 0) {
                atomicAdd(&scnt[lab4.x], 1); atomicAdd(&scnt[lab4.y], 1);
                atomicAdd(&scnt[lab4.z], 1); atomicAdd(&scnt[lab4.w], 1);
            }
            float4* p;
            p = &rep[lab4.x * D4 + t];
            { float4 a = *p; a.x += v0.x; a.y += v0.y; a.z += v0.z; a.w += v0.w; *p = a; }
            p = &rep[lab4.y * D4 + t];
            { float4 a = *p; a.x += v1.x; a.y += v1.y; a.z += v1.z; a.w += v1.w; *p = a; }
            p = &rep[lab4.z * D4 + t];
            { float4 a = *p; a.x += v2.x; a.y += v2.y; a.z += v2.z; a.w += v2.w; *p = a; }
            p = &rep[lab4.w * D4 + t];
            { float4 a = *p; a.x += v3.x; a.y += v3.y; a.z += v3.z; a.w += v3.w; *p = a; }
        } else {
            for (int j = 0; j < 4 && r0 + j < nrows; j++) {
                int lj = labels[r0 + j];
                float4 v = E4[(size_t)(r0 + j) * D4 + t];
                if (t == 0) atomicAdd(&scnt[lj], 1);
                float4* p = &rep[lj * D4 + t];
                float4 a = *p; a.x += v.x; a.y += v.y; a.z += v.z; a.w += v.w; *p = a;
            }
        }
    }
    __syncthreads();

    for (int i = threadIdx.x; i < NC * D4; i += 512) {
        float4 a = sm4[i];
        float4 b = sm4[NC * D4 + i];
        float4 c = sm4[2 * NC * D4 + i];
        float4 d = sm4[3 * NC * D4 + i];
        a.x += b.x + c.x + d.x;
        a.y += b.y + c.y + d.y;
        a.z += b.z + c.z + d.z;
        a.w += b.w + c.w + d.w;
        g_part4[blockIdx.x * (NC * D4) + i] = a;
    }
    if (threadIdx.x < NC)
        g_cnt_part[blockIdx.x * NC + threadIdx.x] = scnt[threadIdx.x];
}

// ---------------------------------------------------------------------------
// K2: reduce partials -> g_sums4. grid 40 x 128: 4 threads per f4 element.
// ---------------------------------------------------------------------------
__global__ __launch_bounds__(128) void k_reduce() {
    const int i  = blockIdx.x * 32 + (threadIdx.x >> 2);   // f4 element 0..1279
    const int ps = threadIdx.x & 3;
    float4 acc = make_float4(0.f, 0.f, 0.f, 0.f);
#pragma unroll 8
    for (int p = ps; p < SEG_BLOCKS; p += 4) {
        float4 v = g_part4[p * (NC * D4) + i];
        acc.x += v.x; acc.y += v.y; acc.z += v.z; acc.w += v.w;
    }
#pragma unroll
    for (int st = 1; st <= 2; st <<= 1) {
        acc.x += __shfl_xor_sync(0xFFFFFFFFu, acc.x, st);
        acc.y += __shfl_xor_sync(0xFFFFFFFFu, acc.y, st);
        acc.z += __shfl_xor_sync(0xFFFFFFFFu, acc.z, st);
        acc.w += __shfl_xor_sync(0xFFFFFFFFu, acc.w, st);
    }
    if (ps == 0) g_sums4[i] = acc;
}

// ---------------------------------------------------------------------------
// K3: counts -> prototypes -> ||p||^2 ; also zero g_loss for this replay.
// ---------------------------------------------------------------------------
__global__ __launch_bounds__(512) void k_proto() {
    __shared__ float sinv[NC];
    const int tid = threadIdx.x, lane = tid & 31, w = tid >> 5;
    if (w < NC) {
        int s = 0;
        for (int p = lane; p < SEG_BLOCKS; p += 32) s += g_cnt_part[p * NC + w];
#pragma unroll
        for (int st = 16; st >= 1; st >>= 1) s += __shfl_xor_sync(0xFFFFFFFFu, s, st);
        if (lane == 0) sinv[w] = 1.0f / (float)s;
    }
    if (tid == 0) g_loss = 0.f;
    __syncthreads();
    const float* gs = (const float*)g_sums4;
    float*       gp = (float*)g_proto4;
#pragma unroll
    for (int c = 0; c < NC; c++) gp[c * DD + tid] = gs[c * DD + tid] * sinv[c];
    __syncthreads();
    if (w < NC) {
        const float* p = gp + w * DD;
        float acc = 0.f;
        for (int j = lane; j < DD; j += 32) acc = fmaf(p[j], p[j], acc);
#pragma unroll
        for (int st = 16; st >= 1; st >>= 1) acc += __shfl_xor_sync(0xFFFFFFFFu, acc, st);
        if (lane == 0) g_sqp[w] = acc;
    }
}

// ---------------------------------------------------------------------------
// K4: logits + log-softmax + loss — cp.async k-sliced pipeline.
// Block = 128 threads = 16 groups(8 lanes) x 4 rows = 64 rows per block.
// The 512-dim reduction runs in 16 slices of 32 dims; each slice's 64x32 f32
// tile (8KB) is staged by cp.async into a 4-stage smem ring. MLP lives in the
// cp.async queue, not registers -> accum-only register budget, 4 blocks/SM.
// Lane layout: lane = g*8 + ch*4 + dimq (class half ch, dim quarter dimq).
// ---------------------------------------------------------------------------
__global__ __launch_bounds__(128, 4) void k_logits(const float4* __restrict__ E4,
                                                   const int* __restrict__ labels,
                                                   float* __restrict__ out,
                                                   int nrows) {
    extern __shared__ char dynbuf[];           // NSTAGES * SLICE_BYTES
    __shared__ float4 sp[NC * D4];             // 20 KB prototypes
    __shared__ float  ssqp[NC];
    __shared__ float  sloss;

    const int tid = threadIdx.x;
    for (int i = tid; i < NC * D4; i += 128) sp[i] = g_proto4[i];
    if (tid < NC) ssqp[tid] = g_sqp[tid];
    if (tid == 0) sloss = 0.f;

    const int warp = tid >> 5;
    const int lane = tid & 31;
    const int dimq = lane & 3;
    const int ch   = (lane >> 2) & 1;
    const int g    = lane >> 3;
    const unsigned gmask = 0xFFu << (g * 8);

    const int tile_base = blockIdx.x * TILE_ROWS;

    // Staging map: thread covers row (tid>>1), 64B half (tid&1) of each slice.
    const int st_row  = tid >> 1;
    const int st_half = tid & 1;
    const int st_growc = min(tile_base + st_row, nrows - 1);
    const float4* st_src_row = E4 + (size_t)st_growc * D4 + st_half * 4;
    const uint32_t st_dst_base =
        smem_u32(dynbuf) + st_row * (SLICE_F4 * 16) + st_half * 64;

    // Prologue: stage slices 0..NSTAGES-1.
#pragma unroll
    for (int s = 0; s < NSTAGES; s++) {
        const float4* src = st_src_row + s * SLICE_F4;
        uint32_t dst = st_dst_base + s * SLICE_BYTES;
#pragma unroll
        for (int j = 0; j < 4; j++) cp_async16(dst + j * 16, src + j);
        asm volatile("cp.async.commit_group;");
    }
    __syncthreads();   // covers sp/ssqp/sloss init too

    // Compute rows for this thread's group.
    const int r0 = tile_base + warp * 16 + g * 4;
    int  rowc[4];
    bool valid[4];
#pragma unroll
    for (int j = 0; j < 4; j++) {
        int r = r0 + j;
        valid[j] = (r < nrows);
        rowc[j]  = valid[j] ? r : (nrows - 1);
    }
    const int tr = warp * 16 + g * 4;          // row index inside tile

    ull dot[4][5];
#pragma unroll
    for (int j = 0; j < 4; j++)
#pragma unroll
        for (int c = 0; c < 5; c++) dot[j][c] = 0ull;
    ull sq[4] = {0ull, 0ull, 0ull, 0ull};

    const ull* __restrict__ Pc =
        (const ull*)sp + (size_t)(ch * 5) * D4 * 2;   // ull units (8B)

    for (int s = 0; s < NSLICES; s++) {
        asm volatile("cp.async.wait_group %0;" :: "n"(NSTAGES - 1));
        __syncthreads();

        const char* buf = dynbuf + (s & (NSTAGES - 1)) * SLICE_BYTES;
#pragma unroll
        for (int k2 = 0; k2 < 2; k2++) {
            const int fi  = k2 * 4 + dimq;                // f4 within slice
            const int pfi = s * SLICE_F4 + fi;            // f4 within row
            // e from smem: quarter-warp reads its own rows, conflict-free.
            ulonglong2 v0 = *(const ulonglong2*)(buf + (tr + 0) * (SLICE_F4 * 16) + fi * 16);
            ulonglong2 v1 = *(const ulonglong2*)(buf + (tr + 1) * (SLICE_F4 * 16) + fi * 16);
            ulonglong2 v2 = *(const ulonglong2*)(buf + (tr + 2) * (SLICE_F4 * 16) + fi * 16);
            ulonglong2 v3 = *(const ulonglong2*)(buf + (tr + 3) * (SLICE_F4 * 16) + fi * 16);
            sq[0] = fma2(v0.x, v0.x, sq[0]); sq[0] = fma2(v0.y, v0.y, sq[0]);
            sq[1] = fma2(v1.x, v1.x, sq[1]); sq[1] = fma2(v1.y, v1.y, sq[1]);
            sq[2] = fma2(v2.x, v2.x, sq[2]); sq[2] = fma2(v2.y, v2.y, sq[2]);
            sq[3] = fma2(v3.x, v3.x, sq[3]); sq[3] = fma2(v3.y, v3.y, sq[3]);
#pragma unroll
            for (int c = 0; c < 5; c++) {
                const ull* pp = Pc + (size_t)c * D4 * 2 + pfi * 2;
                ull px = pp[0], py = pp[1];
                dot[0][c] = fma2(v0.x, px, dot[0][c]); dot[0][c] = fma2(v0.y, py, dot[0][c]);
                dot[1][c] = fma2(v1.x, px, dot[1][c]); dot[1][c] = fma2(v1.y, py, dot[1][c]);
                dot[2][c] = fma2(v2.x, px, dot[2][c]); dot[2][c] = fma2(v2.y, py, dot[2][c]);
                dot[3][c] = fma2(v3.x, px, dot[3][c]); dot[3][c] = fma2(v3.y, py, dot[3][c]);
            }
        }
        __syncthreads();     // everyone done reading buf before restaging it

        const int sn = s + NSTAGES;
        if (sn < NSLICES) {
            const float4* src = st_src_row + sn * SLICE_F4;
            uint32_t dst = st_dst_base + (s & (NSTAGES - 1)) * SLICE_BYTES;
#pragma unroll
            for (int j = 0; j < 4; j++) cp_async16(dst + j * 16, src + j);
        }
        asm volatile("cp.async.commit_group;");  // commit even if empty: keeps group count in step
    }

    // Epilogue (identical math to R6).
    float lvsum = 0.f;
#pragma unroll
    for (int j = 0; j < 4; j++) {
        float sqe = u64_sum2(sq[j]);
        sqe += __shfl_xor_sync(gmask, sqe, 1);
        sqe += __shfl_xor_sync(gmask, sqe, 2);

        float l[5];
        float m5 = -1e30f;
#pragma unroll
        for (int c = 0; c < 5; c++) {
            float d = u64_sum2(dot[j][c]);
            d += __shfl_xor_sync(gmask, d, 1);
            d += __shfl_xor_sync(gmask, d, 2);
            float d2 = sqe + ssqp[ch * 5 + c] - 2.0f * d;
            float lg = -fmaxf(d2, 0.0f);
            l[c] = lg;
            m5 = fmaxf(m5, lg);
        }
        float m = fmaxf(m5, __shfl_xor_sync(gmask, m5, 4));
        float se5 = 0.f;
#pragma unroll
        for (int c = 0; c < 5; c++) se5 += __expf(l[c] - m);
        float se = se5 + __shfl_xor_sync(gmask, se5, 4);

        const int lab = labels[rowc[j]];
        float lsel5 = 0.f;
#pragma unroll
        for (int c = 0; c < 5; c++)
            if (ch * 5 + c == lab) lsel5 = l[c];
        float lsel = lsel5 + __shfl_xor_sync(gmask, lsel5, 4);

        if (dimq == 0 && valid[j]) {
            float* o = out + 1 + (size_t)rowc[j] * NC + ch * 5;
#pragma unroll
            for (int c = 0; c < 5; c++) o[c] = l[c];
        }
        if (dimq == 0 && ch == 0 && valid[j])
            lvsum += m + __logf(se) - lsel;
    }

#pragma unroll
    for (int st = 16; st >= 1; st >>= 1)
        lvsum += __shfl_xor_sync(0xFFFFFFFFu, lvsum, st);
    if (lane == 0) atomicAdd(&sloss, lvsum);
    __syncthreads();
    if (tid == 0) atomicAdd(&g_loss, sloss);
}

// ---------------------------------------------------------------------------
// K5: finalize loss
// ---------------------------------------------------------------------------
__global__ void k_final(float* __restrict__ out, int nrows) {
    out[0] = g_loss * (1.0f / (float)nrows);
}

extern "C" void kernel_launch(void* const* d_in, const int* in_sizes, int n_in,
                              void* d_out, int out_size) {
    const float* E      = (const float*)d_in[0];
    const int*   labels = (const int*)d_in[1];
    float*       out    = (float*)d_out;
    const int nrows = in_sizes[1];   // 131072

    cudaFuncSetAttribute(k_segsum, cudaFuncAttributeMaxDynamicSharedMemorySize,
                         SEG_SMEM);
    cudaFuncSetAttribute(k_logits, cudaFuncAttributeMaxDynamicSharedMemorySize,
                         PIPE_SMEM);

    k_segsum<<<SEG_BLOCKS, 512, SEG_SMEM>>>((const float4*)E, labels, nrows);
    k_reduce<<<40, 128>>>();
    k_proto<<<1, 512>>>();
    k_logits<<<(nrows + TILE_ROWS - 1) / TILE_ROWS, 128, PIPE_SMEM>>>(
        (const float4*)E, labels, out, nrows);
    k_final<<<1, 1>>>(out, nrows);
}

// round 9
// speedup vs baseline: 1.1687x; 1.1687x over previous
#include <cuda_runtime.h>
#include <cstdint>
#include <cstddef>

#define NC 10
#define DD 512
#define D4 128          // DD/4
#define SEG_BLOCKS 296
#define SEG_GROUPS (SEG_BLOCKS * 4)
#define SEG_SMEM (4 * NC * D4 * 16)   // 81920 bytes

// k_logits warp-autonomous pipeline geometry
#define TILE_ROWS 64                  // per block (4 warps x 16 rows)
#define SLICE_F4  8                   // 8 float4 = 32 dims per slice
#define NSLICES   (D4 / SLICE_F4)     // 16
#define NSTAGES   4
#define WSTAGE_BYTES (16 * SLICE_F4 * 16)      // 2048: one warp's 16-row slice
#define WBUF_BYTES   (NSTAGES * WSTAGE_BYTES)  // 8192 per warp
#define PIPE_SMEM    (4 * WBUF_BYTES)          // 32768 per block

typedef unsigned long long ull;

// Scratch (no cudaMalloc allowed)
__device__ float4 g_part4[SEG_BLOCKS * NC * D4];   // 6.06 MB partial sums
__device__ int    g_cnt_part[SEG_BLOCKS * NC];
__device__ float4 g_sums4[NC * D4];
__device__ float4 g_proto4[NC * D4];
__device__ float  g_sqp[NC];
__device__ float  g_loss;

// Packed f32x2 FMA (Blackwell): elementwise d = a*b + c on two packed floats.
static __device__ __forceinline__ ull fma2(ull a, ull b, ull c) {
    ull d;
    asm("fma.rn.f32x2 %0, %1, %2, %3;" : "=l"(d) : "l"(a), "l"(b), "l"(c));
    return d;
}
static __device__ __forceinline__ float u64_sum2(ull v) {
    float lo, hi;
    asm("mov.b64 {%0,%1}, %2;" : "=f"(lo), "=f"(hi) : "l"(v));
    return lo + hi;
}
static __device__ __forceinline__ uint32_t smem_u32(const void* p) {
    uint32_t a;
    asm("{ .reg .u64 t; cvta.to.shared.u64 t, %1; cvt.u32.u64 %0, t; }"
        : "=r"(a) : "l"(p));
    return a;
}
static __device__ __forceinline__ void cp_async16(uint32_t dst, const void* src) {
    asm volatile("cp.async.cg.shared.global [%0], [%1], 16;"
                 :: "r"(dst), "l"(src));
}

// ---------------------------------------------------------------------------
// K1: segment sums. 512 threads = 4 independent row-groups of 128, each with
// its own 20KB smem replica. Depth-1 software prefetch: 8 LDG.128 in flight
// per thread-quad -> 32KB/SM in flight at 32 warps (Little's law headroom).
// ---------------------------------------------------------------------------
__global__ __launch_bounds__(512) void k_segsum(const float4* __restrict__ E4,
                                                const int* __restrict__ labels,
                                                int nrows) {
    extern __shared__ float4 sm4[];            // [4][NC][D4]
    __shared__ int scnt[NC];
    const int g = threadIdx.x >> 7;            // group 0..3
    const int t = threadIdx.x & 127;           // float4 column
    float4* rep = sm4 + g * (NC * D4);

    if (threadIdx.x < NC) scnt[threadIdx.x] = 0;
#pragma unroll
    for (int c = 0; c < NC; c++) rep[c * D4 + t] = make_float4(0.f, 0.f, 0.f, 0.f);
    __syncthreads();

    const int  gid    = blockIdx.x * 4 + g;
    const long stride = (long)SEG_GROUPS * 4;
    long r = (long)gid * 4;

    int4  lab = make_int4(0, 0, 0, 0);
    float4 v0, v1, v2, v3;
    bool have = (r + 4 <= nrows);
    if (have) {
        lab = *(const int4*)(labels + r);
        v0 = E4[(size_t)(r + 0) * D4 + t];
        v1 = E4[(size_t)(r + 1) * D4 + t];
        v2 = E4[(size_t)(r + 2) * D4 + t];
        v3 = E4[(size_t)(r + 3) * D4 + t];
    }
    while (have) {
        const long rn   = r + stride;
        const bool haven = (rn + 4 <= nrows);
        int4  labn = lab;
        float4 n0 = v0, n1 = v1, n2 = v2, n3 = v3;
        if (haven) {   // prefetch next quad while current RMWs execute
            labn = *(const int4*)(labels + rn);
            n0 = E4[(size_t)(rn + 0) * D4 + t];
            n1 = E4[(size_t)(rn + 1) * D4 + t];
            n2 = E4[(size_t)(rn + 2) * D4 + t];
            n3 = E4[(size_t)(rn + 3) * D4 + t];
        }
        if (t == 0) {
            atomicAdd(&scnt[lab.x], 1); atomicAdd(&scnt[lab.y], 1);
            atomicAdd(&scnt[lab.z], 1); atomicAdd(&scnt[lab.w], 1);
        }
        float4* p;
        p = &rep[lab.x * D4 + t];
        { float4 a = *p; a.x += v0.x; a.y += v0.y; a.z += v0.z; a.w += v0.w; *p = a; }
        p = &rep[lab.y * D4 + t];
        { float4 a = *p; a.x += v1.x; a.y += v1.y; a.z += v1.z; a.w += v1.w; *p = a; }
        p = &rep[lab.z * D4 + t];
        { float4 a = *p; a.x += v2.x; a.y += v2.y; a.z += v2.z; a.w += v2.w; *p = a; }
        p = &rep[lab.w * D4 + t];
        { float4 a = *p; a.x += v3.x; a.y += v3.y; a.z += v3.z; a.w += v3.w; *p = a; }
        r = rn; have = haven;
        lab = labn; v0 = n0; v1 = n1; v2 = n2; v3 = n3;
    }
    // At most one partial quad per group.
    if (r < nrows) {
        for (long rr = r; rr < nrows && rr < r + 4; rr++) {
            int lj = labels[rr];
            float4 v = E4[(size_t)rr * D4 + t];
            if (t == 0) atomicAdd(&scnt[lj], 1);
            float4* p = &rep[lj * D4 + t];
            float4 a = *p; a.x += v.x; a.y += v.y; a.z += v.z; a.w += v.w; *p = a;
        }
    }
    __syncthreads();

    for (int i = threadIdx.x; i < NC * D4; i += 512) {
        float4 a = sm4[i];
        float4 b = sm4[NC * D4 + i];
        float4 c = sm4[2 * NC * D4 + i];
        float4 d = sm4[3 * NC * D4 + i];
        a.x += b.x + c.x + d.x;
        a.y += b.y + c.y + d.y;
        a.z += b.z + c.z + d.z;
        a.w += b.w + c.w + d.w;
        g_part4[blockIdx.x * (NC * D4) + i] = a;
    }
    if (threadIdx.x < NC)
        g_cnt_part[blockIdx.x * NC + threadIdx.x] = scnt[threadIdx.x];
}

// ---------------------------------------------------------------------------
// K2: reduce partials -> g_sums4. grid 40 x 128: 4 threads per f4 element.
// ---------------------------------------------------------------------------
__global__ __launch_bounds__(128) void k_reduce() {
    const int i  = blockIdx.x * 32 + (threadIdx.x >> 2);   // f4 element 0..1279
    const int ps = threadIdx.x & 3;
    float4 acc = make_float4(0.f, 0.f, 0.f, 0.f);
#pragma unroll 8
    for (int p = ps; p < SEG_BLOCKS; p += 4) {
        float4 v = g_part4[p * (NC * D4) + i];
        acc.x += v.x; acc.y += v.y; acc.z += v.z; acc.w += v.w;
    }
#pragma unroll
    for (int st = 1; st <= 2; st <<= 1) {
        acc.x += __shfl_xor_sync(0xFFFFFFFFu, acc.x, st);
        acc.y += __shfl_xor_sync(0xFFFFFFFFu, acc.y, st);
        acc.z += __shfl_xor_sync(0xFFFFFFFFu, acc.z, st);
        acc.w += __shfl_xor_sync(0xFFFFFFFFu, acc.w, st);
    }
    if (ps == 0) g_sums4[i] = acc;
}

// ---------------------------------------------------------------------------
// K3: counts -> prototypes -> ||p||^2 ; also zero g_loss for this replay.
// ---------------------------------------------------------------------------
__global__ __launch_bounds__(512) void k_proto() {
    __shared__ float sinv[NC];
    const int tid = threadIdx.x, lane = tid & 31, w = tid >> 5;
    if (w < NC) {
        int s = 0;
        for (int p = lane; p < SEG_BLOCKS; p += 32) s += g_cnt_part[p * NC + w];
#pragma unroll
        for (int st = 16; st >= 1; st >>= 1) s += __shfl_xor_sync(0xFFFFFFFFu, s, st);
        if (lane == 0) sinv[w] = 1.0f / (float)s;
    }
    if (tid == 0) g_loss = 0.f;
    __syncthreads();
    const float* gs = (const float*)g_sums4;
    float*       gp = (float*)g_proto4;
#pragma unroll
    for (int c = 0; c < NC; c++) gp[c * DD + tid] = gs[c * DD + tid] * sinv[c];
    __syncthreads();
    if (w < NC) {
        const float* p = gp + w * DD;
        float acc = 0.f;
        for (int j = lane; j < DD; j += 32) acc = fmaf(p[j], p[j], acc);
#pragma unroll
        for (int st = 16; st >= 1; st >>= 1) acc += __shfl_xor_sync(0xFFFFFFFFu, acc, st);
        if (lane == 0) g_sqp[w] = acc;
    }
}

// ---------------------------------------------------------------------------
// K4: logits + log-softmax + loss — WARP-AUTONOMOUS cp.async pipeline.
// Each warp owns 16 rows and a private 8KB 4-stage smem ring; the 512-dim dot
// runs in 16 slices of 32 dims. cp.async commit/wait are per-thread, so the
// only sync in the main loop is __syncwarp() — no block barriers, pipeline
// never drains. In-flight/SM = 16 warps x 3 slices x 2KB = 96KB >> 24KB
// Little's-law requirement -> DRAM-limited.
// Lane layout: lane = g*8 + ch*4 + dimq; group g owns 4 rows.
// ---------------------------------------------------------------------------
__global__ __launch_bounds__(128, 4) void k_logits(const float4* __restrict__ E4,
                                                   const int* __restrict__ labels,
                                                   float* __restrict__ out,
                                                   int nrows) {
    extern __shared__ char dynbuf[];           // [4 warps][NSTAGES][2048]
    __shared__ float4 sp[NC * D4];             // 20 KB prototypes
    __shared__ float  ssqp[NC];
    __shared__ float  sloss;

    const int tid = threadIdx.x;
    for (int i = tid; i < NC * D4; i += 128) sp[i] = g_proto4[i];
    if (tid < NC) ssqp[tid] = g_sqp[tid];
    if (tid == 0) sloss = 0.f;

    const int warp = tid >> 5;
    const int lane = tid & 31;
    const int dimq = lane & 3;
    const int ch   = (lane >> 2) & 1;
    const int g    = lane >> 3;
    const unsigned gmask = 0xFFu << (g * 8);

    const int wrow0 = blockIdx.x * TILE_ROWS + warp * 16;  // warp's first row
    char* wbuf = dynbuf + warp * WBUF_BYTES;

    // Staging map: lane covers row (lane>>1), 64B half (lane&1) of each slice.
    const int st_row  = lane >> 1;
    const int st_half = lane & 1;
    const int st_growc = min(wrow0 + st_row, nrows - 1);
    const float4* st_src_row = E4 + (size_t)st_growc * D4 + st_half * 4;
    const uint32_t st_dst_base =
        smem_u32(wbuf) + st_row * (SLICE_F4 * 16) + st_half * 64;

    __syncthreads();   // sp/ssqp/sloss visible to all warps before compute

    // Prologue: stage slices 0..NSTAGES-1 (per-warp, per-thread groups).
#pragma unroll
    for (int s = 0; s < NSTAGES; s++) {
        const float4* src = st_src_row + s * SLICE_F4;
        uint32_t dst = st_dst_base + s * WSTAGE_BYTES;
#pragma unroll
        for (int j = 0; j < 4; j++) cp_async16(dst + j * 16, src + j);
        asm volatile("cp.async.commit_group;");
    }

    // This thread's 4 rows.
    const int r0 = wrow0 + g * 4;
    int  rowc[4];
    bool valid[4];
#pragma unroll
    for (int j = 0; j < 4; j++) {
        int r = r0 + j;
        valid[j] = (r < nrows);
        rowc[j]  = valid[j] ? r : (nrows - 1);
    }
    const int tr = g * 4;   // row index within warp's 16-row tile

    ull dot[4][5];
#pragma unroll
    for (int j = 0; j < 4; j++)
#pragma unroll
        for (int c = 0; c < 5; c++) dot[j][c] = 0ull;
    ull sq[4] = {0ull, 0ull, 0ull, 0ull};

    const ull* __restrict__ Pc =
        (const ull*)sp + (size_t)(ch * 5) * D4 * 2;   // ull units (8B)

    for (int s = 0; s < NSLICES; s++) {
        asm volatile("cp.async.wait_group %0;" :: "n"(NSTAGES - 1));
        __syncwarp();

        const char* buf = wbuf + (s & (NSTAGES - 1)) * WSTAGE_BYTES;
#pragma unroll
        for (int k2 = 0; k2 < 2; k2++) {
            const int fi  = k2 * 4 + dimq;                // f4 within slice
            const int pfi = s * SLICE_F4 + fi;            // f4 within row
            ulonglong2 v0 = *(const ulonglong2*)(buf + (tr + 0) * (SLICE_F4 * 16) + fi * 16);
            ulonglong2 v1 = *(const ulonglong2*)(buf + (tr + 1) * (SLICE_F4 * 16) + fi * 16);
            ulonglong2 v2 = *(const ulonglong2*)(buf + (tr + 2) * (SLICE_F4 * 16) + fi * 16);
            ulonglong2 v3 = *(const ulonglong2*)(buf + (tr + 3) * (SLICE_F4 * 16) + fi * 16);
            sq[0] = fma2(v0.x, v0.x, sq[0]); sq[0] = fma2(v0.y, v0.y, sq[0]);
            sq[1] = fma2(v1.x, v1.x, sq[1]); sq[1] = fma2(v1.y, v1.y, sq[1]);
            sq[2] = fma2(v2.x, v2.x, sq[2]); sq[2] = fma2(v2.y, v2.y, sq[2]);
            sq[3] = fma2(v3.x, v3.x, sq[3]); sq[3] = fma2(v3.y, v3.y, sq[3]);
#pragma unroll
            for (int c = 0; c < 5; c++) {
                const ull* pp = Pc + (size_t)c * D4 * 2 + pfi * 2;
                ull px = pp[0], py = pp[1];
                dot[0][c] = fma2(v0.x, px, dot[0][c]); dot[0][c] = fma2(v0.y, py, dot[0][c]);
                dot[1][c] = fma2(v1.x, px, dot[1][c]); dot[1][c] = fma2(v1.y, py, dot[1][c]);
                dot[2][c] = fma2(v2.x, px, dot[2][c]); dot[2][c] = fma2(v2.y, py, dot[2][c]);
                dot[3][c] = fma2(v3.x, px, dot[3][c]); dot[3][c] = fma2(v3.y, py, dot[3][c]);
            }
        }
        __syncwarp();   // warp done reading this stage before restaging it

        const int sn = s + NSTAGES;
        if (sn < NSLICES) {
            const float4* src = st_src_row + sn * SLICE_F4;
            uint32_t dst = st_dst_base + (s & (NSTAGES - 1)) * WSTAGE_BYTES;
#pragma unroll
            for (int j = 0; j < 4; j++) cp_async16(dst + j * 16, src + j);
        }
        asm volatile("cp.async.commit_group;");  // empty groups keep count in step
    }

    // Epilogue (R6 math; 8-lane gmask shuffles, reconverged warp reduce).
    float lvsum = 0.f;
#pragma unroll
    for (int j = 0; j < 4; j++) {
        float sqe = u64_sum2(sq[j]);
        sqe += __shfl_xor_sync(gmask, sqe, 1);
        sqe += __shfl_xor_sync(gmask, sqe, 2);

        float l[5];
        float m5 = -1e30f;
#pragma unroll
        for (int c = 0; c < 5; c++) {
            float d = u64_sum2(dot[j][c]);
            d += __shfl_xor_sync(gmask, d, 1);
            d += __shfl_xor_sync(gmask, d, 2);
            float d2 = sqe + ssqp[ch * 5 + c] - 2.0f * d;
            float lg = -fmaxf(d2, 0.0f);
            l[c] = lg;
            m5 = fmaxf(m5, lg);
        }
        float m = fmaxf(m5, __shfl_xor_sync(gmask, m5, 4));
        float se5 = 0.f;
#pragma unroll
        for (int c = 0; c < 5; c++) se5 += __expf(l[c] - m);
        float se = se5 + __shfl_xor_sync(gmask, se5, 4);

        const int lab = labels[rowc[j]];
        float lsel5 = 0.f;
#pragma unroll
        for (int c = 0; c < 5; c++)
            if (ch * 5 + c == lab) lsel5 = l[c];
        float lsel = lsel5 + __shfl_xor_sync(gmask, lsel5, 4);

        if (dimq == 0 && valid[j]) {
            float* o = out + 1 + (size_t)rowc[j] * NC + ch * 5;
#pragma unroll
            for (int c = 0; c < 5; c++) o[c] = l[c];
        }
        if (dimq == 0 && ch == 0 && valid[j])
            lvsum += m + __logf(se) - lsel;
    }

#pragma unroll
    for (int st = 16; st >= 1; st >>= 1)
        lvsum += __shfl_xor_sync(0xFFFFFFFFu, lvsum, st);
    if (lane == 0) atomicAdd(&sloss, lvsum);
    __syncthreads();
    if (tid == 0) atomicAdd(&g_loss, sloss);
}

// ---------------------------------------------------------------------------
// K5: finalize loss
// ---------------------------------------------------------------------------
__global__ void k_final(float* __restrict__ out, int nrows) {
    out[0] = g_loss * (1.0f / (float)nrows);
}

extern "C" void kernel_launch(void* const* d_in, const int* in_sizes, int n_in,
                              void* d_out, int out_size) {
    const float* E      = (const float*)d_in[0];
    const int*   labels = (const int*)d_in[1];
    float*       out    = (float*)d_out;
    const int nrows = in_sizes[1];   // 131072

    cudaFuncSetAttribute(k_segsum, cudaFuncAttributeMaxDynamicSharedMemorySize,
                         SEG_SMEM);
    cudaFuncSetAttribute(k_logits, cudaFuncAttributeMaxDynamicSharedMemorySize,
                         PIPE_SMEM);

    k_segsum<<<SEG_BLOCKS, 512, SEG_SMEM>>>((const float4*)E, labels, nrows);
    k_reduce<<<40, 128>>>();
    k_proto<<<1, 512>>>();
    k_logits<<<(nrows + TILE_ROWS - 1) / TILE_ROWS, 128, PIPE_SMEM>>>(
        (const float4*)E, labels, out, nrows);
    k_final<<<1, 1>>>(out, nrows);
}